// round 1
// baseline (speedup 1.0000x reference)
#include <cuda_runtime.h>
#include <math.h>

// Problem constants
#define B_  2
#define N_  4096
#define C_  1024
#define H_  16
#define D_  64
#define K_  256
#define HD_ 1024          // H_*D_
#define M_  8192          // B_*N_

// -------------------- device scratch (no runtime allocation allowed) ------
__device__ float g_Q[M_ * HD_];
__device__ float g_K[M_ * HD_];
__device__ float g_V[M_ * HD_];
__device__ float g_KE[B_ * K_ * HD_];   // [b][k][hd]
__device__ float g_VF[B_ * K_ * HD_];   // [b][k][hd]
__device__ float g_O[M_ * HD_];

// ==========================================================================
// SGEMM  C[M,Nn] = A[M,Kc] * B[Nn,Kc]^T  (+ optional bias over columns)
// 128x128 tile, BK=8, 256 threads, 8x8 microtile per thread.
// Requires M%128==0, Nn%128==0, Kc%8==0.
// ==========================================================================
template<int BIAS_COL>
__global__ void sgemm_abt(const float* __restrict__ A,
                          const float* __restrict__ Bm,
                          const float* __restrict__ bias,
                          float* __restrict__ Cc,
                          int Mm, int Nn, int Kc)
{
    __shared__ float As[8][128];
    __shared__ float Bs[8][128];

    const int tid = threadIdx.x;
    const int mt  = blockIdx.y * 128;
    const int nt  = blockIdx.x * 128;

    const int arow = tid >> 1;        // 0..127
    const int acol = (tid & 1) * 4;   // 0 or 4

    const float* Aptr = A  + (size_t)(mt + arow) * Kc + acol;
    const float* Bptr = Bm + (size_t)(nt + arow) * Kc + acol;

    const int tx = tid & 15;
    const int ty = tid >> 4;

    float acc[8][8];
#pragma unroll
    for (int i = 0; i < 8; i++)
#pragma unroll
        for (int j = 0; j < 8; j++) acc[i][j] = 0.f;

    for (int kt = 0; kt < Kc; kt += 8) {
        float4 av = *(const float4*)(Aptr + kt);
        float4 bv = *(const float4*)(Bptr + kt);
        __syncthreads();
        As[acol + 0][arow] = av.x;
        As[acol + 1][arow] = av.y;
        As[acol + 2][arow] = av.z;
        As[acol + 3][arow] = av.w;
        Bs[acol + 0][arow] = bv.x;
        Bs[acol + 1][arow] = bv.y;
        Bs[acol + 2][arow] = bv.z;
        Bs[acol + 3][arow] = bv.w;
        __syncthreads();
#pragma unroll
        for (int k = 0; k < 8; k++) {
            float ra[8], rb[8];
#pragma unroll
            for (int i = 0; i < 8; i++) ra[i] = As[k][ty * 8 + i];
#pragma unroll
            for (int j = 0; j < 8; j++) rb[j] = Bs[k][tx * 8 + j];
#pragma unroll
            for (int i = 0; i < 8; i++)
#pragma unroll
                for (int j = 0; j < 8; j++) acc[i][j] += ra[i] * rb[j];
        }
    }

#pragma unroll
    for (int i = 0; i < 8; i++) {
        const int row = mt + ty * 8 + i;
#pragma unroll
        for (int j = 0; j < 8; j++) {
            const int col = nt + tx * 8 + j;
            float v = acc[i][j];
            if (BIAS_COL) v += bias[col];
            Cc[(size_t)row * Nn + col] = v;
        }
    }
}

// ==========================================================================
// Batched SGEMM NN with row-bias:
//   for b in [0,B_): C[b][M,Nn] = A[M,Kc] * X[b][Kc,Nn]  + bias[row m]
// A is shared across batches (the We/Wf weight). X batch stride = Kc*Nn.
// Same tiling as above. Requires M%128==0, Nn%128==0, Kc%8==0.
// ==========================================================================
__global__ void sgemm_nn_brow(const float* __restrict__ A,
                              const float* __restrict__ X,
                              const float* __restrict__ bias,
                              float* __restrict__ Cc,
                              int Mm, int Nn, int Kc)
{
    __shared__ float As[8][128];
    __shared__ float Bs[8][128];

    const int tid = threadIdx.x;
    const int b   = blockIdx.z;
    const int mt  = blockIdx.y * 128;
    const int nt  = blockIdx.x * 128;

    const float* Xb = X  + (size_t)b * Kc * Nn;
    float*       Cb = Cc + (size_t)b * Mm * Nn;

    const int arow = tid >> 1;
    const int acol = (tid & 1) * 4;
    const float* Aptr = A + (size_t)(mt + arow) * Kc + acol;

    const int brow = tid >> 5;          // 0..7 (k within tile)
    const int bcol = (tid & 31) * 4;    // 0..124

    const int tx = tid & 15;
    const int ty = tid >> 4;

    float acc[8][8];
#pragma unroll
    for (int i = 0; i < 8; i++)
#pragma unroll
        for (int j = 0; j < 8; j++) acc[i][j] = 0.f;

    for (int kt = 0; kt < Kc; kt += 8) {
        float4 av = *(const float4*)(Aptr + kt);
        float4 bv = *(const float4*)(Xb + (size_t)(kt + brow) * Nn + nt + bcol);
        __syncthreads();
        As[acol + 0][arow] = av.x;
        As[acol + 1][arow] = av.y;
        As[acol + 2][arow] = av.z;
        As[acol + 3][arow] = av.w;
        *(float4*)&Bs[brow][bcol] = bv;
        __syncthreads();
#pragma unroll
        for (int k = 0; k < 8; k++) {
            float ra[8], rb[8];
#pragma unroll
            for (int i = 0; i < 8; i++) ra[i] = As[k][ty * 8 + i];
#pragma unroll
            for (int j = 0; j < 8; j++) rb[j] = Bs[k][tx * 8 + j];
#pragma unroll
            for (int i = 0; i < 8; i++)
#pragma unroll
                for (int j = 0; j < 8; j++) acc[i][j] += ra[i] * rb[j];
        }
    }

#pragma unroll
    for (int i = 0; i < 8; i++) {
        const int row = mt + ty * 8 + i;
        const float bv = bias[row];
#pragma unroll
        for (int j = 0; j < 8; j++) {
            const int col = nt + tx * 8 + j;
            Cb[(size_t)row * Nn + col] = acc[i][j] + bv;
        }
    }
}

// ==========================================================================
// Fused low-rank attention:
//   scores[n,k] = (1/8) * sum_d Q[b,n,h*64+d] * KE[b][k][h*64+d]
//   P = softmax_k(scores)
//   O[b,n,h*64+d] = sum_k P[n,k] * VF[b][k][h*64+d]
// One block per (chunk, h, b). KE_h / VF_h tiles resident in smem.
// Warp-per-row, 8 warps, 256 threads. CHUNKS=8 -> 512 rows/block, 256 blocks.
// ==========================================================================
#define ATT_CHUNKS 8
#define ATT_ROWS   (N_ / ATT_CHUNKS)     // 512
#define KE_LD      257                   // padded stride (conflict-free)

// smem floats: KEs 64*257, VFs 256*64, qs 8*64, ps 8*256
#define ATT_SMEM_FLOATS (64 * KE_LD + K_ * D_ + 8 * 64 + 8 * K_)
#define ATT_SMEM_BYTES  (ATT_SMEM_FLOATS * 4)

__global__ void attn_kernel(const float* __restrict__ Q,
                            const float* __restrict__ KE,
                            const float* __restrict__ VF,
                            float* __restrict__ O)
{
    extern __shared__ float sm[];
    float* KEs = sm;                         // [64][257]  (d-major, padded)
    float* VFs = KEs + 64 * KE_LD;           // [256][64]  (k-major)
    float* qs  = VFs + K_ * D_;              // [8][64]
    float* ps  = qs + 8 * 64;                // [8][256]

    const int tid  = threadIdx.x;
    const int lane = tid & 31;
    const int w    = tid >> 5;
    const int b    = blockIdx.z;
    const int h    = blockIdx.y;
    const int n0   = blockIdx.x * ATT_ROWS;

    const float* KEb = KE + (size_t)b * K_ * HD_ + h * D_;
    const float* VFb = VF + (size_t)b * K_ * HD_ + h * D_;

    for (int idx = tid; idx < K_ * D_; idx += 256) {
        const int k = idx >> 6;
        const int d = idx & 63;
        KEs[d * KE_LD + k] = KEb[(size_t)k * HD_ + d];
        VFs[idx]           = VFb[(size_t)k * HD_ + d];
    }
    __syncthreads();

    float* qw = qs + w * 64;
    float* pw = ps + w * K_;

    for (int n = n0 + w; n < n0 + ATT_ROWS; n += 8) {
        const float* qrow = Q + (size_t)(b * N_ + n) * HD_ + h * D_;
        qw[lane]      = qrow[lane];
        qw[lane + 32] = qrow[lane + 32];
        __syncwarp();

        // scores: 8 per lane (k = j*32 + lane)
        float s[8];
#pragma unroll
        for (int j = 0; j < 8; j++) s[j] = 0.f;
#pragma unroll 8
        for (int d = 0; d < 64; d++) {
            const float qd = qw[d];
            const float* ker = KEs + d * KE_LD;
#pragma unroll
            for (int j = 0; j < 8; j++) s[j] += qd * ker[j * 32 + lane];
        }
#pragma unroll
        for (int j = 0; j < 8; j++) s[j] *= 0.125f;

        // softmax over 256 (warp-wide)
        float mx = s[0];
#pragma unroll
        for (int j = 1; j < 8; j++) mx = fmaxf(mx, s[j]);
#pragma unroll
        for (int o = 16; o; o >>= 1) mx = fmaxf(mx, __shfl_xor_sync(0xffffffffu, mx, o));

        float e[8], sum = 0.f;
#pragma unroll
        for (int j = 0; j < 8; j++) { e[j] = __expf(s[j] - mx); sum += e[j]; }
#pragma unroll
        for (int o = 16; o; o >>= 1) sum += __shfl_xor_sync(0xffffffffu, sum, o);

        const float inv = 1.0f / sum;
#pragma unroll
        for (int j = 0; j < 8; j++) pw[j * 32 + lane] = e[j] * inv;
        __syncwarp();

        // out[d] = sum_k p[k] * VF[k][d], each lane handles d=lane, d=lane+32
        float a0 = 0.f, a1 = 0.f;
#pragma unroll 8
        for (int k = 0; k < K_; k++) {
            const float pk = pw[k];
            a0 += pk * VFs[k * 64 + lane];
            a1 += pk * VFs[k * 64 + lane + 32];
        }
        float* orow = O + (size_t)(b * N_ + n) * HD_ + h * D_;
        orow[lane]      = a0;
        orow[lane + 32] = a1;
        // shfl_xor barriers above already re-converged the warp before qw reuse
    }
}

// ==========================================================================
// Host launcher
// ==========================================================================
extern "C" void kernel_launch(void* const* d_in, const int* in_sizes, int n_in,
                              void* d_out, int out_size)
{
    const float* X  = (const float*)d_in[0];
    const float* Wq = (const float*)d_in[1];
    const float* Wk = (const float*)d_in[2];
    const float* Wv = (const float*)d_in[3];
    const float* We = (const float*)d_in[4];
    const float* be = (const float*)d_in[5];
    const float* Wf = (const float*)d_in[6];
    const float* bf = (const float*)d_in[7];
    const float* Wo = (const float*)d_in[8];
    const float* bo = (const float*)d_in[9];
    float* out = (float*)d_out;

    float *Qp, *Kp, *Vp, *KEp, *VFp, *Op;
    cudaGetSymbolAddress((void**)&Qp,  g_Q);
    cudaGetSymbolAddress((void**)&Kp,  g_K);
    cudaGetSymbolAddress((void**)&Vp,  g_V);
    cudaGetSymbolAddress((void**)&KEp, g_KE);
    cudaGetSymbolAddress((void**)&VFp, g_VF);
    cudaGetSymbolAddress((void**)&Op,  g_O);

    cudaFuncSetAttribute(attn_kernel,
                         cudaFuncAttributeMaxDynamicSharedMemorySize,
                         ATT_SMEM_BYTES);

    const dim3 gproj(HD_ / 128, M_ / 128);   // (8, 64)

    // QKV projections: [8192,1024] = X[8192,1024] * W[1024,1024]^T
    sgemm_abt<0><<<gproj, 256>>>(X, Wq, nullptr, Qp, M_, HD_, C_);
    sgemm_abt<0><<<gproj, 256>>>(X, Wk, nullptr, Kp, M_, HD_, C_);
    sgemm_abt<0><<<gproj, 256>>>(X, Wv, nullptr, Vp, M_, HD_, C_);

    // KE[b][k][hd] = We[k,:] . K[b,:,hd] + be[k]   (and same for VF)
    const dim3 glr(HD_ / 128, K_ / 128, B_);  // (8, 2, 2)
    sgemm_nn_brow<<<glr, 256>>>(We, Kp, be, KEp, K_, HD_, N_);
    sgemm_nn_brow<<<glr, 256>>>(Wf, Vp, bf, VFp, K_, HD_, N_);

    // fused scores -> softmax -> PV
    attn_kernel<<<dim3(ATT_CHUNKS, H_, B_), 256, ATT_SMEM_BYTES>>>(Qp, KEp, VFp, Op);

    // output projection: out[8192,1024] = O[8192,1024] * Wo[1024,1024]^T + bo
    sgemm_abt<1><<<gproj, 256>>>(Op, Wo, bo, out, M_, C_, HD_);
}

// round 2
// speedup vs baseline: 1.0032x; 1.0032x over previous
#include <cuda_runtime.h>
#include <math.h>

// Problem constants
#define B_  2
#define N_  4096
#define C_  1024
#define H_  16
#define D_  64
#define K_  256
#define HD_ 1024          // H_*D_
#define M_  8192          // B_*N_

// -------------------- device scratch (no runtime allocation allowed) ------
__device__ float g_Q[M_ * HD_];
__device__ float g_K[M_ * HD_];
__device__ float g_V[M_ * HD_];
__device__ float g_KE[B_ * K_ * HD_];   // [b][k][hd]
__device__ float g_VF[B_ * K_ * HD_];   // [b][k][hd]
__device__ float g_O[M_ * HD_];

// ==========================================================================
// SGEMM  C[M,Nn] = A[M,Kc] * B[Nn,Kc]^T  (+ optional bias over columns)
// 128x128 tile, BK=8, 256 threads, 8x8 microtile per thread.
// Requires M%128==0, Nn%128==0, Kc%8==0.
// ==========================================================================
template<int BIAS_COL>
__global__ void sgemm_abt(const float* __restrict__ A,
                          const float* __restrict__ Bm,
                          const float* __restrict__ bias,
                          float* __restrict__ Cc,
                          int Mm, int Nn, int Kc)
{
    __shared__ float As[8][128];
    __shared__ float Bs[8][128];

    const int tid = threadIdx.x;
    const int mt  = blockIdx.y * 128;
    const int nt  = blockIdx.x * 128;

    const int arow = tid >> 1;        // 0..127
    const int acol = (tid & 1) * 4;   // 0 or 4

    const float* Aptr = A  + (size_t)(mt + arow) * Kc + acol;
    const float* Bptr = Bm + (size_t)(nt + arow) * Kc + acol;

    const int tx = tid & 15;
    const int ty = tid >> 4;

    float acc[8][8];
#pragma unroll
    for (int i = 0; i < 8; i++)
#pragma unroll
        for (int j = 0; j < 8; j++) acc[i][j] = 0.f;

    for (int kt = 0; kt < Kc; kt += 8) {
        float4 av = *(const float4*)(Aptr + kt);
        float4 bv = *(const float4*)(Bptr + kt);
        __syncthreads();
        As[acol + 0][arow] = av.x;
        As[acol + 1][arow] = av.y;
        As[acol + 2][arow] = av.z;
        As[acol + 3][arow] = av.w;
        Bs[acol + 0][arow] = bv.x;
        Bs[acol + 1][arow] = bv.y;
        Bs[acol + 2][arow] = bv.z;
        Bs[acol + 3][arow] = bv.w;
        __syncthreads();
#pragma unroll
        for (int k = 0; k < 8; k++) {
            float ra[8], rb[8];
#pragma unroll
            for (int i = 0; i < 8; i++) ra[i] = As[k][ty * 8 + i];
#pragma unroll
            for (int j = 0; j < 8; j++) rb[j] = Bs[k][tx * 8 + j];
#pragma unroll
            for (int i = 0; i < 8; i++)
#pragma unroll
                for (int j = 0; j < 8; j++) acc[i][j] += ra[i] * rb[j];
        }
    }

#pragma unroll
    for (int i = 0; i < 8; i++) {
        const int row = mt + ty * 8 + i;
#pragma unroll
        for (int j = 0; j < 8; j++) {
            const int col = nt + tx * 8 + j;
            float v = acc[i][j];
            if (BIAS_COL) v += bias[col];
            Cc[(size_t)row * Nn + col] = v;
        }
    }
}

// ==========================================================================
// Batched SGEMM NN with row-bias:
//   for b in [0,B_): C[b][M,Nn] = A[M,Kc] * X[b][Kc,Nn]  + bias[row m]
// A is shared across batches (the We/Wf weight). X batch stride = Kc*Nn.
// Same tiling as above. Requires M%128==0, Nn%128==0, Kc%8==0.
// ==========================================================================
__global__ void sgemm_nn_brow(const float* __restrict__ A,
                              const float* __restrict__ X,
                              const float* __restrict__ bias,
                              float* __restrict__ Cc,
                              int Mm, int Nn, int Kc)
{
    __shared__ float As[8][128];
    __shared__ float Bs[8][128];

    const int tid = threadIdx.x;
    const int b   = blockIdx.z;
    const int mt  = blockIdx.y * 128;
    const int nt  = blockIdx.x * 128;

    const float* Xb = X  + (size_t)b * Kc * Nn;
    float*       Cb = Cc + (size_t)b * Mm * Nn;

    const int arow = tid >> 1;
    const int acol = (tid & 1) * 4;
    const float* Aptr = A + (size_t)(mt + arow) * Kc + acol;

    const int brow = tid >> 5;          // 0..7 (k within tile)
    const int bcol = (tid & 31) * 4;    // 0..124

    const int tx = tid & 15;
    const int ty = tid >> 4;

    float acc[8][8];
#pragma unroll
    for (int i = 0; i < 8; i++)
#pragma unroll
        for (int j = 0; j < 8; j++) acc[i][j] = 0.f;

    for (int kt = 0; kt < Kc; kt += 8) {
        float4 av = *(const float4*)(Aptr + kt);
        float4 bv = *(const float4*)(Xb + (size_t)(kt + brow) * Nn + nt + bcol);
        __syncthreads();
        As[acol + 0][arow] = av.x;
        As[acol + 1][arow] = av.y;
        As[acol + 2][arow] = av.z;
        As[acol + 3][arow] = av.w;
        *(float4*)&Bs[brow][bcol] = bv;
        __syncthreads();
#pragma unroll
        for (int k = 0; k < 8; k++) {
            float ra[8], rb[8];
#pragma unroll
            for (int i = 0; i < 8; i++) ra[i] = As[k][ty * 8 + i];
#pragma unroll
            for (int j = 0; j < 8; j++) rb[j] = Bs[k][tx * 8 + j];
#pragma unroll
            for (int i = 0; i < 8; i++)
#pragma unroll
                for (int j = 0; j < 8; j++) acc[i][j] += ra[i] * rb[j];
        }
    }

#pragma unroll
    for (int i = 0; i < 8; i++) {
        const int row = mt + ty * 8 + i;
        const float bv = bias[row];
#pragma unroll
        for (int j = 0; j < 8; j++) {
            const int col = nt + tx * 8 + j;
            Cb[(size_t)row * Nn + col] = acc[i][j] + bv;
        }
    }
}

// ==========================================================================
// Fused low-rank attention:
//   scores[n,k] = (1/8) * sum_d Q[b,n,h*64+d] * KE[b][k][h*64+d]
//   P = softmax_k(scores)
//   O[b,n,h*64+d] = sum_k P[n,k] * VF[b][k][h*64+d]
// One block per (chunk, h, b). KE_h / VF_h tiles resident in smem.
// Warp-per-row, 8 warps, 256 threads. CHUNKS=8 -> 512 rows/block, 256 blocks.
// ==========================================================================
#define ATT_CHUNKS 8
#define ATT_ROWS   (N_ / ATT_CHUNKS)     // 512
#define KE_LD      257                   // padded stride (conflict-free)

// smem floats: KEs 64*257, VFs 256*64, qs 8*64, ps 8*256
#define ATT_SMEM_FLOATS (64 * KE_LD + K_ * D_ + 8 * 64 + 8 * K_)
#define ATT_SMEM_BYTES  (ATT_SMEM_FLOATS * 4)

__global__ void attn_kernel(const float* __restrict__ Q,
                            const float* __restrict__ KE,
                            const float* __restrict__ VF,
                            float* __restrict__ O)
{
    extern __shared__ float sm[];
    float* KEs = sm;                         // [64][257]  (d-major, padded)
    float* VFs = KEs + 64 * KE_LD;           // [256][64]  (k-major)
    float* qs  = VFs + K_ * D_;              // [8][64]
    float* ps  = qs + 8 * 64;                // [8][256]

    const int tid  = threadIdx.x;
    const int lane = tid & 31;
    const int w    = tid >> 5;
    const int b    = blockIdx.z;
    const int h    = blockIdx.y;
    const int n0   = blockIdx.x * ATT_ROWS;

    const float* KEb = KE + (size_t)b * K_ * HD_ + h * D_;
    const float* VFb = VF + (size_t)b * K_ * HD_ + h * D_;

    for (int idx = tid; idx < K_ * D_; idx += 256) {
        const int k = idx >> 6;
        const int d = idx & 63;
        KEs[d * KE_LD + k] = KEb[(size_t)k * HD_ + d];
        VFs[idx]           = VFb[(size_t)k * HD_ + d];
    }
    __syncthreads();

    float* qw = qs + w * 64;
    float* pw = ps + w * K_;

    for (int n = n0 + w; n < n0 + ATT_ROWS; n += 8) {
        const float* qrow = Q + (size_t)(b * N_ + n) * HD_ + h * D_;
        qw[lane]      = qrow[lane];
        qw[lane + 32] = qrow[lane + 32];
        __syncwarp();

        // scores: 8 per lane (k = j*32 + lane)
        float s[8];
#pragma unroll
        for (int j = 0; j < 8; j++) s[j] = 0.f;
#pragma unroll 8
        for (int d = 0; d < 64; d++) {
            const float qd = qw[d];
            const float* ker = KEs + d * KE_LD;
#pragma unroll
            for (int j = 0; j < 8; j++) s[j] += qd * ker[j * 32 + lane];
        }
#pragma unroll
        for (int j = 0; j < 8; j++) s[j] *= 0.125f;

        // softmax over 256 (warp-wide)
        float mx = s[0];
#pragma unroll
        for (int j = 1; j < 8; j++) mx = fmaxf(mx, s[j]);
#pragma unroll
        for (int o = 16; o; o >>= 1) mx = fmaxf(mx, __shfl_xor_sync(0xffffffffu, mx, o));

        float e[8], sum = 0.f;
#pragma unroll
        for (int j = 0; j < 8; j++) { e[j] = __expf(s[j] - mx); sum += e[j]; }
#pragma unroll
        for (int o = 16; o; o >>= 1) sum += __shfl_xor_sync(0xffffffffu, sum, o);

        const float inv = 1.0f / sum;
#pragma unroll
        for (int j = 0; j < 8; j++) pw[j * 32 + lane] = e[j] * inv;
        __syncwarp();

        // out[d] = sum_k p[k] * VF[k][d], each lane handles d=lane, d=lane+32
        float a0 = 0.f, a1 = 0.f;
#pragma unroll 8
        for (int k = 0; k < K_; k++) {
            const float pk = pw[k];
            a0 += pk * VFs[k * 64 + lane];
            a1 += pk * VFs[k * 64 + lane + 32];
        }
        float* orow = O + (size_t)(b * N_ + n) * HD_ + h * D_;
        orow[lane]      = a0;
        orow[lane + 32] = a1;
        // shfl_xor barriers above already re-converged the warp before qw reuse
    }
}

// ==========================================================================
// Host launcher
// ==========================================================================
extern "C" void kernel_launch(void* const* d_in, const int* in_sizes, int n_in,
                              void* d_out, int out_size)
{
    const float* X  = (const float*)d_in[0];
    const float* Wq = (const float*)d_in[1];
    const float* Wk = (const float*)d_in[2];
    const float* Wv = (const float*)d_in[3];
    const float* We = (const float*)d_in[4];
    const float* be = (const float*)d_in[5];
    const float* Wf = (const float*)d_in[6];
    const float* bf = (const float*)d_in[7];
    const float* Wo = (const float*)d_in[8];
    const float* bo = (const float*)d_in[9];
    float* out = (float*)d_out;

    float *Qp, *Kp, *Vp, *KEp, *VFp, *Op;
    cudaGetSymbolAddress((void**)&Qp,  g_Q);
    cudaGetSymbolAddress((void**)&Kp,  g_K);
    cudaGetSymbolAddress((void**)&Vp,  g_V);
    cudaGetSymbolAddress((void**)&KEp, g_KE);
    cudaGetSymbolAddress((void**)&VFp, g_VF);
    cudaGetSymbolAddress((void**)&Op,  g_O);

    cudaFuncSetAttribute(attn_kernel,
                         cudaFuncAttributeMaxDynamicSharedMemorySize,
                         ATT_SMEM_BYTES);

    const dim3 gproj(HD_ / 128, M_ / 128);   // (8, 64)

    // QKV projections: [8192,1024] = X[8192,1024] * W[1024,1024]^T
    sgemm_abt<0><<<gproj, 256>>>(X, Wq, nullptr, Qp, M_, HD_, C_);
    sgemm_abt<0><<<gproj, 256>>>(X, Wk, nullptr, Kp, M_, HD_, C_);
    sgemm_abt<0><<<gproj, 256>>>(X, Wv, nullptr, Vp, M_, HD_, C_);

    // KE[b][k][hd] = We[k,:] . K[b,:,hd] + be[k]   (and same for VF)
    const dim3 glr(HD_ / 128, K_ / 128, B_);  // (8, 2, 2)
    sgemm_nn_brow<<<glr, 256>>>(We, Kp, be, KEp, K_, HD_, N_);
    sgemm_nn_brow<<<glr, 256>>>(Wf, Vp, bf, VFp, K_, HD_, N_);

    // fused scores -> softmax -> PV
    attn_kernel<<<dim3(ATT_CHUNKS, H_, B_), 256, ATT_SMEM_BYTES>>>(Qp, KEp, VFp, Op);

    // output projection: out[8192,1024] = O[8192,1024] * Wo[1024,1024]^T + bo
    sgemm_abt<1><<<gproj, 256>>>(Op, Wo, bo, out, M_, C_, HD_);
}

// round 4
// speedup vs baseline: 4.7172x; 4.7022x over previous
#include <cuda_runtime.h>
#include <cuda_fp16.h>
#include <cstdint>

#define B_  2
#define N_  4096
#define C_  1024
#define H_  16
#define D_  64
#define K_  256
#define HD_ 1024
#define M_  8192

__device__ float g_Q  [M_ * HD_];
__device__ float g_Kt [B_ * HD_ * N_];
__device__ float g_Vt [B_ * HD_ * N_];
__device__ float g_KE [B_ * K_ * HD_];
__device__ float g_VFt[B_ * HD_ * K_];
__device__ float g_O  [M_ * HD_];
__device__ float g_part[8 * K_ * HD_];

#define DEV __device__ __forceinline__

DEV uint32_t su32(const void* p) {
    uint32_t a;
    asm("{ .reg .u64 t; cvta.to.shared.u64 t, %1; cvt.u32.u64 %0, t; }" : "=r"(a) : "l"(p));
    return a;
}

// split fp32 pair into packed fp16 (big) and fp16 (residual) halves
DEV void splitf(float x, float y, uint32_t& bo, uint32_t& so) {
    __half hx = __float2half_rn(x), hy = __float2half_rn(y);
    __half2 hb = __halves2half2(hx, hy);
    bo = *(uint32_t*)&hb;
    __half2 hs = __floats2half2_rn(x - __half2float(hx), y - __half2float(hy));
    so = *(uint32_t*)&hs;
}

#define LDM4(r, a) \
    asm volatile("ldmatrix.sync.aligned.m8n8.x4.shared.b16 {%0,%1,%2,%3}, [%4];" \
        : "=r"((r)[0]), "=r"((r)[1]), "=r"((r)[2]), "=r"((r)[3]) : "r"(a))

DEV void mma16816(float* d, const uint32_t* a, const uint32_t* b) {
    asm volatile("mma.sync.aligned.m16n8k16.row.col.f32.f16.f16.f32 "
        "{%0,%1,%2,%3}, {%4,%5,%6,%7}, {%8,%9}, {%0,%1,%2,%3};"
        : "+f"(d[0]), "+f"(d[1]), "+f"(d[2]), "+f"(d[3])
        : "r"(a[0]), "r"(a[1]), "r"(a[2]), "r"(a[3]), "r"(b[0]), "r"(b[1]));
}

// ==========================================================================
// Projection GEMM: C[M,N] = A[M,K] * B[N,K]^T (+bias), fp16 3-term split mma
// 128x128 tile, BK=32, 256 threads, warp tile 64x32 (2x4 warp grid)
// ==========================================================================
#define ASTR 40                   // smem row stride in halves (padded)
#define BUF  (128 * ASTR)         // halves per buffer (5120)
#define GEMM_SMEM (2 * 4 * BUF * 2)  // 81920 bytes

template<int BIAS>   // 0 none, 1 per-col, 2 per-row
__global__ void __launch_bounds__(256, 1)
mma_gemm(const float* __restrict__ A, const float* __restrict__ Bm,
         const float* __restrict__ bias, float* __restrict__ Cc,
         int ldA, int ldB, int ldC, int Kdim,
         long zA, long zB, long zC, int splitk)
{
    extern __shared__ __half sh[];
    const int tid = threadIdx.x, wid = tid >> 5, lane = tid & 31;

    long aOff, bOff, cOff;
    if (splitk) {
        int zb = blockIdx.z >> 2, ks = blockIdx.z & 3;
        aOff = (long)zb * zA + ks * 1024;
        bOff = (long)zb * zB + ks * 1024;
        cOff = (long)blockIdx.z * zC;
    } else {
        aOff = (long)blockIdx.z * zA;
        bOff = (long)blockIdx.z * zB;
        cOff = (long)blockIdx.z * zC;
    }
    const float* Ag = A  + aOff + (size_t)(blockIdx.y * 128) * ldA;
    const float* Bg = Bm + bOff + (size_t)(blockIdx.x * 128) * ldB;
    float*       Cg = Cc + cOff;

    const int wm = (wid >> 2) * 64, wn = (wid & 3) * 32;
    const int lr = tid >> 3, lc = (tid & 7) * 4;   // per-thread load row/col

    float acc[4][4][4];
#pragma unroll
    for (int m = 0; m < 4; m++)
#pragma unroll
        for (int n = 0; n < 4; n++)
#pragma unroll
            for (int j = 0; j < 4; j++) acc[m][n][j] = 0.f;

    float4 ra[4], rb[4];

    auto LOAD = [&](int kt) {
#pragma unroll
        for (int p = 0; p < 4; p++) {
            ra[p] = *(const float4*)(Ag + (size_t)(lr + p * 32) * ldA + kt * 32 + lc);
            rb[p] = *(const float4*)(Bg + (size_t)(lr + p * 32) * ldB + kt * 32 + lc);
        }
    };
    auto STORE = [&](int s) {
        __half* Ab = sh + s * 4 * BUF;
#pragma unroll
        for (int p = 0; p < 4; p++) {
            const int off = (lr + p * 32) * ASTR + lc;
            uint32_t b0, s0, b1, s1;
            splitf(ra[p].x, ra[p].y, b0, s0); splitf(ra[p].z, ra[p].w, b1, s1);
            *(uint32_t*)(Ab + off) = b0;             *(uint32_t*)(Ab + off + 2) = b1;
            *(uint32_t*)(Ab + BUF + off) = s0;       *(uint32_t*)(Ab + BUF + off + 2) = s1;
            splitf(rb[p].x, rb[p].y, b0, s0); splitf(rb[p].z, rb[p].w, b1, s1);
            *(uint32_t*)(Ab + 2 * BUF + off) = b0;   *(uint32_t*)(Ab + 2 * BUF + off + 2) = b1;
            *(uint32_t*)(Ab + 3 * BUF + off) = s0;   *(uint32_t*)(Ab + 3 * BUF + off + 2) = s1;
        }
    };
    const uint32_t shb = su32(sh);
    const uint32_t aoff = ((wm + (lane & 15)) * ASTR + 8 * (lane >> 4)) * 2;
    const uint32_t boff = ((wn + (lane & 7) + 8 * (lane >> 4)) * ASTR + 8 * ((lane >> 3) & 1)) * 2;

    auto COMPUTE = [&](int s) {
        const uint32_t base = shb + s * 4 * BUF * 2;
#pragma unroll
        for (int ks = 0; ks < 32; ks += 16) {
            uint32_t ab[4][4], as_[4][4];
#pragma unroll
            for (int m = 0; m < 4; m++) {
                const uint32_t ad = base + aoff + (m * 16 * ASTR + ks) * 2;
                LDM4(ab[m], ad);
                LDM4(as_[m], ad + BUF * 2);
            }
#pragma unroll
            for (int np = 0; np < 2; np++) {
                const uint32_t bd = base + 2 * BUF * 2 + boff + (np * 16 * ASTR + ks) * 2;
                uint32_t bb[4], bs[4];
                LDM4(bb, bd);
                LDM4(bs, bd + BUF * 2);
#pragma unroll
                for (int m = 0; m < 4; m++) {
                    mma16816(acc[m][2 * np],     ab[m],  bb);
                    mma16816(acc[m][2 * np],     ab[m],  bs);
                    mma16816(acc[m][2 * np],     as_[m], bb);
                    mma16816(acc[m][2 * np + 1], ab[m],  bb + 2);
                    mma16816(acc[m][2 * np + 1], ab[m],  bs + 2);
                    mma16816(acc[m][2 * np + 1], as_[m], bb + 2);
                }
            }
        }
    };

    const int NK = Kdim >> 5;
    LOAD(0); STORE(0); __syncthreads();
    for (int kt = 0; kt < NK; kt++) {
        if (kt + 1 < NK) LOAD(kt + 1);
        COMPUTE(kt & 1);
        if (kt + 1 < NK) STORE((kt + 1) & 1);
        __syncthreads();
    }

    const int row0 = blockIdx.y * 128 + wm + (lane >> 2);
    const int col0 = blockIdx.x * 128 + wn + 2 * (lane & 3);
#pragma unroll
    for (int m = 0; m < 4; m++) {
#pragma unroll
        for (int n = 0; n < 4; n++) {
            const int r = row0 + m * 16, c = col0 + n * 8;
            float v0 = acc[m][n][0], v1 = acc[m][n][1];
            float v2 = acc[m][n][2], v3 = acc[m][n][3];
            if (BIAS == 1) {
                const float bc0 = __ldg(&bias[c]), bc1 = __ldg(&bias[c + 1]);
                v0 += bc0; v1 += bc1; v2 += bc0; v3 += bc1;
            } else if (BIAS == 2) {
                const float br0 = __ldg(&bias[r]), br1 = __ldg(&bias[r + 8]);
                v0 += br0; v1 += br0; v2 += br1; v3 += br1;
            }
            *(float2*)&Cg[(size_t)r * ldC + c]       = make_float2(v0, v1);
            *(float2*)&Cg[(size_t)(r + 8) * ldC + c] = make_float2(v2, v3);
        }
    }
}

// ==========================================================================
// Split-K reduce (+bias)
// ==========================================================================
__global__ void reduce_bias(const float* __restrict__ part, const float* __restrict__ bias,
                            float* __restrict__ dst, int cols, int biasCol)
{
    const int per = (K_ * HD_) / 4;
    const int i = blockIdx.x * 256 + threadIdx.x;
    const int b = blockIdx.y;
    const float4* p = (const float4*)part + (size_t)b * 4 * per;
    float4 v = p[i];
    float4 v1 = p[per + i], v2 = p[2 * per + i], v3 = p[3 * per + i];
    v.x += v1.x + v2.x + v3.x; v.y += v1.y + v2.y + v3.y;
    v.z += v1.z + v2.z + v3.z; v.w += v1.w + v2.w + v3.w;
    const int e = i * 4;
    if (biasCol) {
        const int c = e % cols;
        v.x += bias[c]; v.y += bias[c + 1]; v.z += bias[c + 2]; v.w += bias[c + 3];
    } else {
        const float bb = bias[e / cols];
        v.x += bb; v.y += bb; v.z += bb; v.w += bb;
    }
    ((float4*)dst)[(size_t)b * per + i] = v;
}

// ==========================================================================
// Fused attention (mma): CTA = (128 rows, head h, batch b), 8 warps
//   warp owns 16 rows: S[16,256] = Q*KE^T (3-pass), softmax in regs,
//   O[16,64] = P*VFt^T with P C-frag -> A-frag register reuse (3-pass)
// ==========================================================================
#define QSTR 72
#define VSTR 264
#define OQB 0
#define OQS (128 * QSTR)
#define OKB (2 * 128 * QSTR)
#define OKS (OKB + 256 * QSTR)
#define OVB (OKS + 256 * QSTR)
#define OVS (OVB + 64 * VSTR)
#define ATT_SMEM ((OVS + 64 * VSTR) * 2)   // 178176 bytes

__global__ void __launch_bounds__(256, 1)
attn_mma(const float* __restrict__ Q, const float* __restrict__ KE,
         const float* __restrict__ VFt, float* __restrict__ O)
{
    extern __shared__ __half sh[];
    const int tid = threadIdx.x, wid = tid >> 5, lane = tid & 31;
    const int b = blockIdx.z, h = blockIdx.y, n0 = blockIdx.x * 128;

    const float* Qg = Q   + ((size_t)(b * N_ + n0)) * HD_ + h * D_;
    const float* Kg = KE  + ((size_t)b * K_) * HD_ + h * D_;
    const float* Vg = VFt + ((size_t)(b * HD_ + h * D_)) * K_;

    {   // Q + KE: rows of 64 floats = 16 float4s
        const int c4 = (tid & 15) * 4, r0 = tid >> 4;
#pragma unroll
        for (int p = 0; p < 8; p++) {
            const int r = r0 + p * 16;
            float4 v = *(const float4*)(Qg + (size_t)r * HD_ + c4);
            const int off = r * QSTR + c4;
            uint32_t b0, s0, b1, s1;
            splitf(v.x, v.y, b0, s0); splitf(v.z, v.w, b1, s1);
            *(uint32_t*)(sh + OQB + off) = b0; *(uint32_t*)(sh + OQB + off + 2) = b1;
            *(uint32_t*)(sh + OQS + off) = s0; *(uint32_t*)(sh + OQS + off + 2) = s1;
        }
#pragma unroll
        for (int p = 0; p < 16; p++) {
            const int r = r0 + p * 16;
            float4 v = *(const float4*)(Kg + (size_t)r * HD_ + c4);
            const int off = r * QSTR + c4;
            uint32_t b0, s0, b1, s1;
            splitf(v.x, v.y, b0, s0); splitf(v.z, v.w, b1, s1);
            *(uint32_t*)(sh + OKB + off) = b0; *(uint32_t*)(sh + OKB + off + 2) = b1;
            *(uint32_t*)(sh + OKS + off) = s0; *(uint32_t*)(sh + OKS + off + 2) = s1;
        }
        const int vc4 = (tid & 63) * 4, vr0 = tid >> 6;
#pragma unroll
        for (int p = 0; p < 16; p++) {
            const int r = vr0 + p * 4;
            float4 v = *(const float4*)(Vg + (size_t)r * K_ + vc4);
            const int off = r * VSTR + vc4;
            uint32_t b0, s0, b1, s1;
            splitf(v.x, v.y, b0, s0); splitf(v.z, v.w, b1, s1);
            *(uint32_t*)(sh + OVB + off) = b0; *(uint32_t*)(sh + OVB + off + 2) = b1;
            *(uint32_t*)(sh + OVS + off) = s0; *(uint32_t*)(sh + OVS + off + 2) = s1;
        }
    }
    __syncthreads();

    // ---- scores: warp rows r0..r0+15, cols 0..255
    float sacc[32][4];
#pragma unroll
    for (int j = 0; j < 32; j++)
#pragma unroll
        for (int q = 0; q < 4; q++) sacc[j][q] = 0.f;

    const uint32_t shb = su32(sh);
    const int r0 = wid * 16;
    const uint32_t aoff = ((r0 + (lane & 15)) * QSTR + 8 * (lane >> 4)) * 2;
    const uint32_t boff = (((lane & 7) + 8 * (lane >> 4)) * QSTR + 8 * ((lane >> 3) & 1)) * 2;

#pragma unroll
    for (int ks = 0; ks < 64; ks += 16) {
        uint32_t ab[4], as_[4];
        LDM4(ab,  shb + OQB * 2 + aoff + ks * 2);
        LDM4(as_, shb + OQS * 2 + aoff + ks * 2);
#pragma unroll
        for (int np = 0; np < 16; np++) {
            uint32_t kb[4], ksm[4];
            const uint32_t bd = boff + (np * 16 * QSTR + ks) * 2;
            LDM4(kb,  shb + OKB * 2 + bd);
            LDM4(ksm, shb + OKS * 2 + bd);
            mma16816(sacc[2 * np],     ab,  kb);
            mma16816(sacc[2 * np],     ab,  ksm);
            mma16816(sacc[2 * np],     as_, kb);
            mma16816(sacc[2 * np + 1], ab,  kb + 2);
            mma16816(sacc[2 * np + 1], ab,  ksm + 2);
            mma16816(sacc[2 * np + 1], as_, kb + 2);
        }
    }

    // ---- softmax (rows r0 + lane/4 and +8), scale 1/8 folded into exp
    float mx0 = -1e30f, mx1 = -1e30f;
#pragma unroll
    for (int j = 0; j < 32; j++) {
        mx0 = fmaxf(mx0, fmaxf(sacc[j][0], sacc[j][1]));
        mx1 = fmaxf(mx1, fmaxf(sacc[j][2], sacc[j][3]));
    }
    mx0 = fmaxf(mx0, __shfl_xor_sync(0xffffffffu, mx0, 1));
    mx0 = fmaxf(mx0, __shfl_xor_sync(0xffffffffu, mx0, 2));
    mx1 = fmaxf(mx1, __shfl_xor_sync(0xffffffffu, mx1, 1));
    mx1 = fmaxf(mx1, __shfl_xor_sync(0xffffffffu, mx1, 2));
    float sum0 = 0.f, sum1 = 0.f;
#pragma unroll
    for (int j = 0; j < 32; j++) {
        float e0 = __expf((sacc[j][0] - mx0) * 0.125f);
        float e1 = __expf((sacc[j][1] - mx0) * 0.125f);
        float e2 = __expf((sacc[j][2] - mx1) * 0.125f);
        float e3 = __expf((sacc[j][3] - mx1) * 0.125f);
        sacc[j][0] = e0; sacc[j][1] = e1; sacc[j][2] = e2; sacc[j][3] = e3;
        sum0 += e0 + e1; sum1 += e2 + e3;
    }
    sum0 += __shfl_xor_sync(0xffffffffu, sum0, 1);
    sum0 += __shfl_xor_sync(0xffffffffu, sum0, 2);
    sum1 += __shfl_xor_sync(0xffffffffu, sum1, 1);
    sum1 += __shfl_xor_sync(0xffffffffu, sum1, 2);
    const float inv0 = 1.0f / sum0, inv1 = 1.0f / sum1;
#pragma unroll
    for (int j = 0; j < 32; j++) {
        sacc[j][0] *= inv0; sacc[j][1] *= inv0;
        sacc[j][2] *= inv1; sacc[j][3] *= inv1;
    }

    // ---- PV: O[16,64] = P * VFt^T, P split on-the-fly from fp32 accums
    float oacc[8][4];
#pragma unroll
    for (int n = 0; n < 8; n++)
#pragma unroll
        for (int q = 0; q < 4; q++) oacc[n][q] = 0.f;

#pragma unroll
    for (int kt = 0; kt < 16; kt++) {
        uint32_t pa[4], ps[4];
        splitf(sacc[2 * kt][0],     sacc[2 * kt][1],     pa[0], ps[0]);
        splitf(sacc[2 * kt][2],     sacc[2 * kt][3],     pa[1], ps[1]);
        splitf(sacc[2 * kt + 1][0], sacc[2 * kt + 1][1], pa[2], ps[2]);
        splitf(sacc[2 * kt + 1][2], sacc[2 * kt + 1][3], pa[3], ps[3]);
#pragma unroll
        for (int np = 0; np < 4; np++) {
            const uint32_t bd = (((lane & 7) + 8 * (lane >> 4) + np * 16) * VSTR
                                 + kt * 16 + 8 * ((lane >> 3) & 1)) * 2;
            uint32_t vb[4], vs[4];
            LDM4(vb, shb + OVB * 2 + bd);
            LDM4(vs, shb + OVS * 2 + bd);
            mma16816(oacc[2 * np],     pa, vb);
            mma16816(oacc[2 * np],     pa, vs);
            mma16816(oacc[2 * np],     ps, vb);
            mma16816(oacc[2 * np + 1], pa, vb + 2);
            mma16816(oacc[2 * np + 1], pa, vs + 2);
            mma16816(oacc[2 * np + 1], ps, vb + 2);
        }
    }

    // ---- store O
    const int orow = n0 + r0 + (lane >> 2);
    const int ocol = h * D_ + 2 * (lane & 3);
    float* Ob = O + ((size_t)b * N_) * HD_;
#pragma unroll
    for (int n = 0; n < 8; n++) {
        *(float2*)&Ob[(size_t)orow * HD_ + ocol + n * 8]       = make_float2(oacc[n][0], oacc[n][1]);
        *(float2*)&Ob[(size_t)(orow + 8) * HD_ + ocol + n * 8] = make_float2(oacc[n][2], oacc[n][3]);
    }
}

// ==========================================================================
extern "C" void kernel_launch(void* const* d_in, const int* in_sizes, int n_in,
                              void* d_out, int out_size)
{
    const float* X  = (const float*)d_in[0];
    const float* Wq = (const float*)d_in[1];
    const float* Wk = (const float*)d_in[2];
    const float* Wv = (const float*)d_in[3];
    const float* We = (const float*)d_in[4];
    const float* be = (const float*)d_in[5];
    const float* Wf = (const float*)d_in[6];
    const float* bf = (const float*)d_in[7];
    const float* Wo = (const float*)d_in[8];
    const float* bo = (const float*)d_in[9];
    float* out = (float*)d_out;

    float *Qp, *Ktp, *Vtp, *KEp, *VFp, *Op, *Pp;
    cudaGetSymbolAddress((void**)&Qp,  g_Q);
    cudaGetSymbolAddress((void**)&Ktp, g_Kt);
    cudaGetSymbolAddress((void**)&Vtp, g_Vt);
    cudaGetSymbolAddress((void**)&KEp, g_KE);
    cudaGetSymbolAddress((void**)&VFp, g_VFt);
    cudaGetSymbolAddress((void**)&Op,  g_O);
    cudaGetSymbolAddress((void**)&Pp,  g_part);

    cudaFuncSetAttribute(mma_gemm<0>, cudaFuncAttributeMaxDynamicSharedMemorySize, GEMM_SMEM);
    cudaFuncSetAttribute(mma_gemm<1>, cudaFuncAttributeMaxDynamicSharedMemorySize, GEMM_SMEM);
    cudaFuncSetAttribute(attn_mma,    cudaFuncAttributeMaxDynamicSharedMemorySize, ATT_SMEM);

    // Q = X * Wq^T                               [8192, 1024]
    mma_gemm<0><<<dim3(8, 64, 1), 256, GEMM_SMEM>>>(X, Wq, nullptr, Qp,
        1024, 1024, 1024, 1024, 0, 0, 0, 0);
    // Kt[b] = Wk * X_b^T                         [1024, 4096] per b
    mma_gemm<0><<<dim3(32, 8, B_), 256, GEMM_SMEM>>>(Wk, X, nullptr, Ktp,
        1024, 1024, 4096, 1024, 0, (long)N_ * C_, (long)HD_ * N_, 0);
    // Vt[b] = Wv * X_b^T
    mma_gemm<0><<<dim3(32, 8, B_), 256, GEMM_SMEM>>>(Wv, X, nullptr, Vtp,
        1024, 1024, 4096, 1024, 0, (long)N_ * C_, (long)HD_ * N_, 0);
    // KE partials (split-K x4): We * Kt[b]^T     [256, 1024]
    mma_gemm<0><<<dim3(8, 2, 8), 256, GEMM_SMEM>>>(We, Ktp, nullptr, Pp,
        4096, 4096, 1024, 1024, 0, (long)HD_ * N_, (long)K_ * HD_, 1);
    reduce_bias<<<dim3((K_ * HD_ / 4) / 256, B_), 256>>>(Pp, be, KEp, HD_, 0);
    // VFt partials (split-K x4): Vt[b] * Wf^T    [1024, 256]
    mma_gemm<0><<<dim3(2, 8, 8), 256, GEMM_SMEM>>>(Vtp, Wf, nullptr, Pp,
        4096, 4096, 256, 1024, (long)HD_ * N_, 0, (long)HD_ * K_, 1);
    reduce_bias<<<dim3((HD_ * K_ / 4) / 256, B_), 256>>>(Pp, bf, VFp, K_, 1);
    // fused attention
    attn_mma<<<dim3(N_ / 128, H_, B_), 256, ATT_SMEM>>>(Qp, KEp, VFp, Op);
    // out = O * Wo^T + bo                        [8192, 1024]
    mma_gemm<1><<<dim3(8, 64, 1), 256, GEMM_SMEM>>>(Op, Wo, bo, out,
        1024, 1024, 1024, 1024, 0, 0, 0, 0);
}

// round 5
// speedup vs baseline: 5.1520x; 1.0922x over previous
#include <cuda_runtime.h>
#include <cuda_fp16.h>
#include <cstdint>

#define B_  2
#define N_  4096
#define C_  1024
#define H_  16
#define D_  64
#define K_  256
#define HD_ 1024
#define M_  8192

// ---------------- persistent split (big/small) fp16 buffers -------------
__device__ __half h_Xb [M_ * C_],    h_Xs [M_ * C_];
__device__ __half h_Wqb[HD_ * C_],   h_Wqs[HD_ * C_];
__device__ __half h_Wkb[HD_ * C_],   h_Wks[HD_ * C_];
__device__ __half h_Wvb[HD_ * C_],   h_Wvs[HD_ * C_];
__device__ __half h_Web[K_ * N_],    h_Wes[K_ * N_];
__device__ __half h_Wfb[K_ * N_],    h_Wfs[K_ * N_];
__device__ __half h_Wob[C_ * HD_],   h_Wos[C_ * HD_];
__device__ __half h_Qb [M_ * HD_],   h_Qs [M_ * HD_];
__device__ __half h_Ktb[B_ * HD_ * N_], h_Kts[B_ * HD_ * N_];
__device__ __half h_Vtb[B_ * HD_ * N_], h_Vts[B_ * HD_ * N_];
__device__ __half h_KEb[B_ * K_ * HD_], h_KEs[B_ * K_ * HD_];
__device__ __half h_VFb[B_ * HD_ * K_], h_VFs[B_ * HD_ * K_];
__device__ __half h_Ob [M_ * HD_],   h_Os [M_ * HD_];
__device__ float  g_part[8 * K_ * HD_];

#define DEV __device__ __forceinline__

DEV uint32_t su32(const void* p) {
    uint32_t a;
    asm("{ .reg .u64 t; cvta.to.shared.u64 t, %1; cvt.u32.u64 %0, t; }" : "=r"(a) : "l"(p));
    return a;
}
DEV void splitf(float x, float y, uint32_t& bo, uint32_t& so) {
    __half hx = __float2half_rn(x), hy = __float2half_rn(y);
    __half2 hb = __halves2half2(hx, hy);
    bo = *(uint32_t*)&hb;
    __half2 hs = __floats2half2_rn(x - __half2float(hx), y - __half2float(hy));
    so = *(uint32_t*)&hs;
}

#define CP16(dst, src) asm volatile("cp.async.cg.shared.global [%0], [%1], 16;" :: "r"(dst), "l"(src) : "memory")
#define CPCOMMIT() asm volatile("cp.async.commit_group;" ::: "memory")
#define CPWAIT0()  asm volatile("cp.async.wait_group 0;" ::: "memory")

#define LDM4(r, a) \
    asm volatile("ldmatrix.sync.aligned.m8n8.x4.shared.b16 {%0,%1,%2,%3}, [%4];" \
        : "=r"((r)[0]), "=r"((r)[1]), "=r"((r)[2]), "=r"((r)[3]) : "r"(a))

DEV void mma16816(float* d, const uint32_t* a, const uint32_t* b) {
    asm volatile("mma.sync.aligned.m16n8k16.row.col.f32.f16.f16.f32 "
        "{%0,%1,%2,%3}, {%4,%5,%6,%7}, {%8,%9}, {%0,%1,%2,%3};"
        : "+f"(d[0]), "+f"(d[1]), "+f"(d[2]), "+f"(d[3])
        : "r"(a[0]), "r"(a[1]), "r"(a[2]), "r"(a[3]), "r"(b[0]), "r"(b[1]));
}

// swizzled byte offset inside a 128x32-half tile (rows of 64B, 16B chunks)
DEV uint32_t tswz(int r, int ch) { return (r << 6) | (((ch ^ ((r >> 1) & 3)) & 3) << 4); }

// ==========================================================================
// split pass: fp32 array -> (big, small) fp16 arrays
// ==========================================================================
__global__ void split_arr(const float* __restrict__ in, __half* __restrict__ ob,
                          __half* __restrict__ os, int n4)
{
    const int i = blockIdx.x * 256 + threadIdx.x;
    if (i >= n4) return;
    float4 v = ((const float4*)in)[i];
    uint32_t b0, s0, b1, s1;
    splitf(v.x, v.y, b0, s0);
    splitf(v.z, v.w, b1, s1);
    ((uint2*)ob)[i] = make_uint2(b0, b1);
    ((uint2*)os)[i] = make_uint2(s0, s1);
}

// ==========================================================================
// fp16 split-GEMM: C[M,N] = (Ab+As)[M,K] * (Bb+Bs)[N,K]^T  (3-term)
// 128x128 tile, BK=32, 256 thr, warp tile 64x32, cp.async 2-stage, swizzled
// EPI: 0 = fp32 out (+opt col bias), 1 = split-half pair out
// ==========================================================================
#define GEMM_SMEM 65536

template<int EPI, int BIASCOL>
__global__ void __launch_bounds__(256, 2)
hgemm(const __half* __restrict__ Ab_, const __half* __restrict__ As_,
      const __half* __restrict__ Bb_, const __half* __restrict__ Bs_,
      const float* __restrict__ bias, float* __restrict__ Cf,
      __half* __restrict__ Cbh, __half* __restrict__ Csh,
      int ldA, int ldB, int ldC, int Kdim,
      long zA, long zB, long zC, int splitk)
{
    extern __shared__ __half sh[];
    const int tid = threadIdx.x, wid = tid >> 5, lane = tid & 31;
    const uint32_t shb = su32(sh);

    long aOff, bOff, cOff;
    if (splitk) {
        int zb = blockIdx.z >> 2, ks = blockIdx.z & 3;
        aOff = (long)zb * zA + ks * 1024;
        bOff = (long)zb * zB + ks * 1024;
        cOff = (long)blockIdx.z * zC;
    } else {
        aOff = (long)blockIdx.z * zA;
        bOff = (long)blockIdx.z * zB;
        cOff = (long)blockIdx.z * zC;
    }
    const __half* Agb = Ab_ + aOff + (size_t)(blockIdx.y * 128) * ldA;
    const __half* Ags = As_ + aOff + (size_t)(blockIdx.y * 128) * ldA;
    const __half* Bgb = Bb_ + bOff + (size_t)(blockIdx.x * 128) * ldB;
    const __half* Bgs = Bs_ + bOff + (size_t)(blockIdx.x * 128) * ldB;

    const int wm = (wid >> 2) * 64, wn = (wid & 3) * 32;

    float acc[4][4][4];
#pragma unroll
    for (int m = 0; m < 4; m++)
#pragma unroll
        for (int n = 0; n < 4; n++)
#pragma unroll
            for (int j = 0; j < 4; j++) acc[m][n][j] = 0.f;

    // stage layout (bytes): Ab@0, As@8192, Bb@16384, Bs@24576; stage stride 32768
    auto PREFETCH = [&](int kt, int s) {
        const uint32_t st = shb + s * 32768;
        const int kc = kt * 32;
#pragma unroll
        for (int p = 0; p < 2; p++) {
            const int id = p * 256 + tid;
            const int r = id >> 2, c = id & 3;
            const uint32_t d = st + tswz(r, c);
            const size_t ga = (size_t)r * ldA + kc + c * 8;
            const size_t gb = (size_t)r * ldB + kc + c * 8;
            CP16(d,         Agb + ga);
            CP16(d +  8192, Ags + ga);
            CP16(d + 16384, Bgb + gb);
            CP16(d + 24576, Bgs + gb);
        }
    };

    auto COMPUTE = [&](int s) {
        const uint32_t base = shb + s * 32768;
#pragma unroll
        for (int ks2 = 0; ks2 < 2; ks2++) {
            uint32_t ab[4][4], as_[4][4];
#pragma unroll
            for (int m = 0; m < 4; m++) {
                const int r = wm + m * 16 + (lane & 15);
                const int ch = ks2 * 2 + (lane >> 4);
                const uint32_t ad = base + tswz(r, ch);
                LDM4(ab[m], ad);
                LDM4(as_[m], ad + 8192);
            }
#pragma unroll
            for (int np = 0; np < 2; np++) {
                const int r = wn + np * 16 + (lane & 7) + 8 * (lane >> 4);
                const int ch = ks2 * 2 + ((lane >> 3) & 1);
                const uint32_t bd = base + 16384 + tswz(r, ch);
                uint32_t bb[4], bs[4];
                LDM4(bb, bd);
                LDM4(bs, bd + 8192);
#pragma unroll
                for (int m = 0; m < 4; m++) {
                    mma16816(acc[m][2 * np],     ab[m],  bb);
                    mma16816(acc[m][2 * np],     ab[m],  bs);
                    mma16816(acc[m][2 * np],     as_[m], bb);
                    mma16816(acc[m][2 * np + 1], ab[m],  bb + 2);
                    mma16816(acc[m][2 * np + 1], ab[m],  bs + 2);
                    mma16816(acc[m][2 * np + 1], as_[m], bb + 2);
                }
            }
        }
    };

    const int NK = Kdim >> 5;
    PREFETCH(0, 0);
    CPCOMMIT();
    for (int kt = 0; kt < NK; kt++) {
        CPWAIT0();
        __syncthreads();
        if (kt + 1 < NK) { PREFETCH(kt + 1, (kt + 1) & 1); CPCOMMIT(); }
        COMPUTE(kt & 1);
    }

    const int row0 = blockIdx.y * 128 + wm + (lane >> 2);
    const int col0 = blockIdx.x * 128 + wn + 2 * (lane & 3);
#pragma unroll
    for (int m = 0; m < 4; m++) {
#pragma unroll
        for (int n = 0; n < 4; n++) {
            const int r = row0 + m * 16, c = col0 + n * 8;
            float v0 = acc[m][n][0], v1 = acc[m][n][1];
            float v2 = acc[m][n][2], v3 = acc[m][n][3];
            if (EPI == 0) {
                if (BIASCOL) {
                    const float bc0 = __ldg(&bias[c]), bc1 = __ldg(&bias[c + 1]);
                    v0 += bc0; v1 += bc1; v2 += bc0; v3 += bc1;
                }
                float* Cg = Cf + cOff;
                *(float2*)&Cg[(size_t)r * ldC + c]       = make_float2(v0, v1);
                *(float2*)&Cg[(size_t)(r + 8) * ldC + c] = make_float2(v2, v3);
            } else {
                __half* Cb = Cbh + cOff;
                __half* Cs = Csh + cOff;
                uint32_t b0, s0, b1, s1;
                splitf(v0, v1, b0, s0);
                splitf(v2, v3, b1, s1);
                *(uint32_t*)&Cb[(size_t)r * ldC + c]       = b0;
                *(uint32_t*)&Cs[(size_t)r * ldC + c]       = s0;
                *(uint32_t*)&Cb[(size_t)(r + 8) * ldC + c] = b1;
                *(uint32_t*)&Cs[(size_t)(r + 8) * ldC + c] = s1;
            }
        }
    }
}

// ==========================================================================
// split-K reduce + bias -> split halves
// ==========================================================================
__global__ void reduce_split(const float* __restrict__ part, const float* __restrict__ bias,
                             __half* __restrict__ ob, __half* __restrict__ os,
                             int cols, int biasCol)
{
    const int per = (K_ * HD_) / 4;
    const int i = blockIdx.x * 256 + threadIdx.x;
    const int b = blockIdx.y;
    const float4* p = (const float4*)part + (size_t)b * 4 * per;
    float4 v = p[i];
    float4 v1 = p[per + i], v2 = p[2 * per + i], v3 = p[3 * per + i];
    v.x += v1.x + v2.x + v3.x; v.y += v1.y + v2.y + v3.y;
    v.z += v1.z + v2.z + v3.z; v.w += v1.w + v2.w + v3.w;
    const int e = i * 4;
    if (biasCol) {
        const int c = e % cols;
        v.x += bias[c]; v.y += bias[c + 1]; v.z += bias[c + 2]; v.w += bias[c + 3];
    } else {
        const float bb = bias[e / cols];
        v.x += bb; v.y += bb; v.z += bb; v.w += bb;
    }
    uint32_t b0, s0, b1, s1;
    splitf(v.x, v.y, b0, s0);
    splitf(v.z, v.w, b1, s1);
    ((uint2*)ob)[(size_t)b * per + i] = make_uint2(b0, b1);
    ((uint2*)os)[(size_t)b * per + i] = make_uint2(s0, s1);
}

// ==========================================================================
// Fused attention: CTA = (128 rows, head h, batch b), 8 warps
// ==========================================================================
#define QSTR 72
#define VSTR 264
#define OQB 0
#define OQS (128 * QSTR)
#define OKB (2 * 128 * QSTR)
#define OKS (OKB + 256 * QSTR)
#define OVB (OKS + 256 * QSTR)
#define OVS (OVB + 64 * VSTR)
#define ATT_SMEM ((OVS + 64 * VSTR) * 2)

__global__ void __launch_bounds__(256, 1)
attn_mma(const __half* __restrict__ Qb, const __half* __restrict__ Qs,
         const __half* __restrict__ KEb, const __half* __restrict__ KEs,
         const __half* __restrict__ VFb, const __half* __restrict__ VFs,
         __half* __restrict__ Ob, __half* __restrict__ Os)
{
    extern __shared__ __half sh[];
    const int tid = threadIdx.x, wid = tid >> 5, lane = tid & 31;
    const int b = blockIdx.z, h = blockIdx.y, n0 = blockIdx.x * 128;
    const uint32_t shb = su32(sh);

    const __half* Qgb = Qb  + ((size_t)(b * N_ + n0)) * HD_ + h * D_;
    const __half* Qgs = Qs  + ((size_t)(b * N_ + n0)) * HD_ + h * D_;
    const __half* Kgb = KEb + ((size_t)b * K_) * HD_ + h * D_;
    const __half* Kgs = KEs + ((size_t)b * K_) * HD_ + h * D_;
    const __half* Vgb = VFb + ((size_t)(b * HD_ + h * D_)) * K_;
    const __half* Vgs = VFs + ((size_t)(b * HD_ + h * D_)) * K_;

#pragma unroll
    for (int p = 0; p < 4; p++) {         // Q: 128 rows x 8 chunks
        const int id = p * 256 + tid;
        const int r = id >> 3, c = id & 7;
        const size_t g = (size_t)r * HD_ + c * 8;
        const uint32_t d = (r * QSTR + c * 8) * 2;
        CP16(shb + OQB * 2 + d, Qgb + g);
        CP16(shb + OQS * 2 + d, Qgs + g);
    }
#pragma unroll
    for (int p = 0; p < 8; p++) {         // KE: 256 rows x 8 chunks
        const int id = p * 256 + tid;
        const int r = id >> 3, c = id & 7;
        const size_t g = (size_t)r * HD_ + c * 8;
        const uint32_t d = (r * QSTR + c * 8) * 2;
        CP16(shb + OKB * 2 + d, Kgb + g);
        CP16(shb + OKS * 2 + d, Kgs + g);
    }
#pragma unroll
    for (int p = 0; p < 8; p++) {         // VF: 64 rows x 32 chunks
        const int id = p * 256 + tid;
        const int r = id >> 5, c = id & 31;
        const size_t g = (size_t)r * K_ + c * 8;
        const uint32_t d = (r * VSTR + c * 8) * 2;
        CP16(shb + OVB * 2 + d, Vgb + g);
        CP16(shb + OVS * 2 + d, Vgs + g);
    }
    CPCOMMIT();
    CPWAIT0();
    __syncthreads();

    // ---- scores
    float sacc[32][4];
#pragma unroll
    for (int j = 0; j < 32; j++)
#pragma unroll
        for (int q = 0; q < 4; q++) sacc[j][q] = 0.f;

    const int r0 = wid * 16;
    const uint32_t aoff = ((r0 + (lane & 15)) * QSTR + 8 * (lane >> 4)) * 2;
    const uint32_t boff = (((lane & 7) + 8 * (lane >> 4)) * QSTR + 8 * ((lane >> 3) & 1)) * 2;

#pragma unroll
    for (int ks = 0; ks < 64; ks += 16) {
        uint32_t ab[4], as_[4];
        LDM4(ab,  shb + OQB * 2 + aoff + ks * 2);
        LDM4(as_, shb + OQS * 2 + aoff + ks * 2);
#pragma unroll
        for (int np = 0; np < 16; np++) {
            uint32_t kb[4], ksm[4];
            const uint32_t bd = boff + (np * 16 * QSTR + ks) * 2;
            LDM4(kb,  shb + OKB * 2 + bd);
            LDM4(ksm, shb + OKS * 2 + bd);
            mma16816(sacc[2 * np],     ab,  kb);
            mma16816(sacc[2 * np],     ab,  ksm);
            mma16816(sacc[2 * np],     as_, kb);
            mma16816(sacc[2 * np + 1], ab,  kb + 2);
            mma16816(sacc[2 * np + 1], ab,  ksm + 2);
            mma16816(sacc[2 * np + 1], as_, kb + 2);
        }
    }

    // ---- softmax
    float mx0 = -1e30f, mx1 = -1e30f;
#pragma unroll
    for (int j = 0; j < 32; j++) {
        mx0 = fmaxf(mx0, fmaxf(sacc[j][0], sacc[j][1]));
        mx1 = fmaxf(mx1, fmaxf(sacc[j][2], sacc[j][3]));
    }
    mx0 = fmaxf(mx0, __shfl_xor_sync(0xffffffffu, mx0, 1));
    mx0 = fmaxf(mx0, __shfl_xor_sync(0xffffffffu, mx0, 2));
    mx1 = fmaxf(mx1, __shfl_xor_sync(0xffffffffu, mx1, 1));
    mx1 = fmaxf(mx1, __shfl_xor_sync(0xffffffffu, mx1, 2));
    float sum0 = 0.f, sum1 = 0.f;
#pragma unroll
    for (int j = 0; j < 32; j++) {
        float e0 = __expf((sacc[j][0] - mx0) * 0.125f);
        float e1 = __expf((sacc[j][1] - mx0) * 0.125f);
        float e2 = __expf((sacc[j][2] - mx1) * 0.125f);
        float e3 = __expf((sacc[j][3] - mx1) * 0.125f);
        sacc[j][0] = e0; sacc[j][1] = e1; sacc[j][2] = e2; sacc[j][3] = e3;
        sum0 += e0 + e1; sum1 += e2 + e3;
    }
    sum0 += __shfl_xor_sync(0xffffffffu, sum0, 1);
    sum0 += __shfl_xor_sync(0xffffffffu, sum0, 2);
    sum1 += __shfl_xor_sync(0xffffffffu, sum1, 1);
    sum1 += __shfl_xor_sync(0xffffffffu, sum1, 2);
    const float inv0 = 1.0f / sum0, inv1 = 1.0f / sum1;
#pragma unroll
    for (int j = 0; j < 32; j++) {
        sacc[j][0] *= inv0; sacc[j][1] *= inv0;
        sacc[j][2] *= inv1; sacc[j][3] *= inv1;
    }

    // ---- PV
    float oacc[8][4];
#pragma unroll
    for (int n = 0; n < 8; n++)
#pragma unroll
        for (int q = 0; q < 4; q++) oacc[n][q] = 0.f;

#pragma unroll
    for (int kt = 0; kt < 16; kt++) {
        uint32_t pa[4], ps[4];
        splitf(sacc[2 * kt][0],     sacc[2 * kt][1],     pa[0], ps[0]);
        splitf(sacc[2 * kt][2],     sacc[2 * kt][3],     pa[1], ps[1]);
        splitf(sacc[2 * kt + 1][0], sacc[2 * kt + 1][1], pa[2], ps[2]);
        splitf(sacc[2 * kt + 1][2], sacc[2 * kt + 1][3], pa[3], ps[3]);
#pragma unroll
        for (int np = 0; np < 4; np++) {
            const uint32_t bd = (((lane & 7) + 8 * (lane >> 4) + np * 16) * VSTR
                                 + kt * 16 + 8 * ((lane >> 3) & 1)) * 2;
            uint32_t vb[4], vs[4];
            LDM4(vb, shb + OVB * 2 + bd);
            LDM4(vs, shb + OVS * 2 + bd);
            mma16816(oacc[2 * np],     pa, vb);
            mma16816(oacc[2 * np],     pa, vs);
            mma16816(oacc[2 * np],     ps, vb);
            mma16816(oacc[2 * np + 1], pa, vb + 2);
            mma16816(oacc[2 * np + 1], pa, vs + 2);
            mma16816(oacc[2 * np + 1], ps, vb + 2);
        }
    }

    // ---- store O as split halves
    const int orow = n0 + r0 + (lane >> 2);
    const int ocol = h * D_ + 2 * (lane & 3);
    __half* Obp = Ob + ((size_t)b * N_) * HD_;
    __half* Osp = Os + ((size_t)b * N_) * HD_;
#pragma unroll
    for (int n = 0; n < 8; n++) {
        uint32_t b0, s0, b1, s1;
        splitf(oacc[n][0], oacc[n][1], b0, s0);
        splitf(oacc[n][2], oacc[n][3], b1, s1);
        *(uint32_t*)&Obp[(size_t)orow * HD_ + ocol + n * 8]       = b0;
        *(uint32_t*)&Osp[(size_t)orow * HD_ + ocol + n * 8]       = s0;
        *(uint32_t*)&Obp[(size_t)(orow + 8) * HD_ + ocol + n * 8] = b1;
        *(uint32_t*)&Osp[(size_t)(orow + 8) * HD_ + ocol + n * 8] = s1;
    }
}

// ==========================================================================
extern "C" void kernel_launch(void* const* d_in, const int* in_sizes, int n_in,
                              void* d_out, int out_size)
{
    const float* X  = (const float*)d_in[0];
    const float* Wq = (const float*)d_in[1];
    const float* Wk = (const float*)d_in[2];
    const float* Wv = (const float*)d_in[3];
    const float* We = (const float*)d_in[4];
    const float* be = (const float*)d_in[5];
    const float* Wf = (const float*)d_in[6];
    const float* bf = (const float*)d_in[7];
    const float* Wo = (const float*)d_in[8];
    const float* bo = (const float*)d_in[9];
    float* out = (float*)d_out;

    __half *Xb, *Xs, *Wqb, *Wqs, *Wkb, *Wks, *Wvb, *Wvs, *Web, *Wes, *Wfb, *Wfs, *Wob, *Wos;
    __half *Qb, *Qs, *Ktb, *Kts, *Vtb, *Vts, *KEbp, *KEsp, *VFbp, *VFsp, *Obp, *Osp;
    float* Pp;
    cudaGetSymbolAddress((void**)&Xb,  h_Xb);  cudaGetSymbolAddress((void**)&Xs,  h_Xs);
    cudaGetSymbolAddress((void**)&Wqb, h_Wqb); cudaGetSymbolAddress((void**)&Wqs, h_Wqs);
    cudaGetSymbolAddress((void**)&Wkb, h_Wkb); cudaGetSymbolAddress((void**)&Wks, h_Wks);
    cudaGetSymbolAddress((void**)&Wvb, h_Wvb); cudaGetSymbolAddress((void**)&Wvs, h_Wvs);
    cudaGetSymbolAddress((void**)&Web, h_Web); cudaGetSymbolAddress((void**)&Wes, h_Wes);
    cudaGetSymbolAddress((void**)&Wfb, h_Wfb); cudaGetSymbolAddress((void**)&Wfs, h_Wfs);
    cudaGetSymbolAddress((void**)&Wob, h_Wob); cudaGetSymbolAddress((void**)&Wos, h_Wos);
    cudaGetSymbolAddress((void**)&Qb,  h_Qb);  cudaGetSymbolAddress((void**)&Qs,  h_Qs);
    cudaGetSymbolAddress((void**)&Ktb, h_Ktb); cudaGetSymbolAddress((void**)&Kts, h_Kts);
    cudaGetSymbolAddress((void**)&Vtb, h_Vtb); cudaGetSymbolAddress((void**)&Vts, h_Vts);
    cudaGetSymbolAddress((void**)&KEbp, h_KEb); cudaGetSymbolAddress((void**)&KEsp, h_KEs);
    cudaGetSymbolAddress((void**)&VFbp, h_VFb); cudaGetSymbolAddress((void**)&VFsp, h_VFs);
    cudaGetSymbolAddress((void**)&Obp, h_Ob);  cudaGetSymbolAddress((void**)&Osp, h_Os);
    cudaGetSymbolAddress((void**)&Pp,  g_part);

    cudaFuncSetAttribute(hgemm<0, 0>, cudaFuncAttributeMaxDynamicSharedMemorySize, GEMM_SMEM);
    cudaFuncSetAttribute(hgemm<0, 1>, cudaFuncAttributeMaxDynamicSharedMemorySize, GEMM_SMEM);
    cudaFuncSetAttribute(hgemm<1, 0>, cudaFuncAttributeMaxDynamicSharedMemorySize, GEMM_SMEM);
    cudaFuncSetAttribute(attn_mma, cudaFuncAttributeMaxDynamicSharedMemorySize, ATT_SMEM);

    // ---- pre-split inputs
    split_arr<<<(M_ * C_ / 4 + 255) / 256, 256>>>(X,  Xb,  Xs,  M_ * C_ / 4);
    split_arr<<<(HD_ * C_ / 4 + 255) / 256, 256>>>(Wq, Wqb, Wqs, HD_ * C_ / 4);
    split_arr<<<(HD_ * C_ / 4 + 255) / 256, 256>>>(Wk, Wkb, Wks, HD_ * C_ / 4);
    split_arr<<<(HD_ * C_ / 4 + 255) / 256, 256>>>(Wv, Wvb, Wvs, HD_ * C_ / 4);
    split_arr<<<(K_ * N_ / 4 + 255) / 256, 256>>>(We, Web, Wes, K_ * N_ / 4);
    split_arr<<<(K_ * N_ / 4 + 255) / 256, 256>>>(Wf, Wfb, Wfs, K_ * N_ / 4);
    split_arr<<<(C_ * HD_ / 4 + 255) / 256, 256>>>(Wo, Wob, Wos, C_ * HD_ / 4);

    // ---- Q = X * Wq^T -> split halves           [8192, 1024]
    hgemm<1, 0><<<dim3(8, 64, 1), 256, GEMM_SMEM>>>(Xb, Xs, Wqb, Wqs, nullptr,
        nullptr, Qb, Qs, 1024, 1024, 1024, 1024, 0, 0, 0, 0);
    // ---- Kt[b] = Wk * X_b^T -> halves           [1024, 4096] per b
    hgemm<1, 0><<<dim3(32, 8, B_), 256, GEMM_SMEM>>>(Wkb, Wks, Xb, Xs, nullptr,
        nullptr, Ktb, Kts, 1024, 1024, 4096, 1024, 0, (long)N_ * C_, (long)HD_ * N_, 0);
    // ---- Vt[b] = Wv * X_b^T -> halves
    hgemm<1, 0><<<dim3(32, 8, B_), 256, GEMM_SMEM>>>(Wvb, Wvs, Xb, Xs, nullptr,
        nullptr, Vtb, Vts, 1024, 1024, 4096, 1024, 0, (long)N_ * C_, (long)HD_ * N_, 0);
    // ---- KE partials (split-K x4): We * Kt^T -> fp32   [256, 1024]
    hgemm<0, 0><<<dim3(8, 2, 8), 256, GEMM_SMEM>>>(Web, Wes, Ktb, Kts, nullptr,
        Pp, nullptr, nullptr, 4096, 4096, 1024, 1024, 0, (long)HD_ * N_, (long)K_ * HD_, 1);
    reduce_split<<<dim3((K_ * HD_ / 4) / 256, B_), 256>>>(Pp, be, KEbp, KEsp, HD_, 0);
    // ---- VFt partials (split-K x4): Vt * Wf^T -> fp32  [1024, 256]
    hgemm<0, 0><<<dim3(2, 8, 8), 256, GEMM_SMEM>>>(Vtb, Vts, Wfb, Wfs, nullptr,
        Pp, nullptr, nullptr, 4096, 4096, 256, 1024, (long)HD_ * N_, 0, (long)HD_ * K_, 1);
    reduce_split<<<dim3((HD_ * K_ / 4) / 256, B_), 256>>>(Pp, bf, VFbp, VFsp, K_, 1);
    // ---- fused attention -> O halves
    attn_mma<<<dim3(N_ / 128, H_, B_), 256, ATT_SMEM>>>(Qb, Qs, KEbp, KEsp, VFbp, VFsp, Obp, Osp);
    // ---- out = O * Wo^T + bo                     [8192, 1024] fp32
    hgemm<0, 1><<<dim3(8, 64, 1), 256, GEMM_SMEM>>>(Obp, Osp, Wob, Wos, bo,
        out, nullptr, nullptr, 1024, 1024, 1024, 1024, 0, 0, 0, 0);
}